// round 1
// baseline (speedup 1.0000x reference)
#include <cuda_runtime.h>
#include <cstdint>

#define BB 64
#define PP 32768
#define OO 50
#define NC 2

// ---------------- scratch (device globals; no allocations allowed) ----------------
__device__ float g_inter[(size_t)BB * PP];
__device__ float g_den[(size_t)BB * PP];
__device__ unsigned char g_tidx[(size_t)BB * PP];
__device__ unsigned long long g_bestprior[BB * OO];
__device__ float g_lcmine[(size_t)BB * PP];
__device__ int g_numpos[BB];
__device__ float g_accum[4];  // 0: loss_l, 1: pos lc sum, 2: neg (mined) lc sum

// ---------------- helpers ----------------
__device__ __forceinline__ float blockReduceSumF(float v, float* sbuf) {
    __syncthreads();
    #pragma unroll
    for (int o = 16; o > 0; o >>= 1) v += __shfl_down_sync(0xffffffffu, v, o);
    int lane = threadIdx.x & 31, w = threadIdx.x >> 5;
    if (lane == 0) sbuf[w] = v;
    __syncthreads();
    int nw = blockDim.x >> 5;
    v = (threadIdx.x < nw) ? sbuf[threadIdx.x] : 0.f;
    if (w == 0) {
        #pragma unroll
        for (int o = 16; o > 0; o >>= 1) v += __shfl_down_sync(0xffffffffu, v, o);
    }
    return v;  // valid on tid 0
}

__device__ __forceinline__ int blockReduceSumI(int v, int* sbuf) {
    __syncthreads();
    #pragma unroll
    for (int o = 16; o > 0; o >>= 1) v += __shfl_down_sync(0xffffffffu, v, o);
    int lane = threadIdx.x & 31, w = threadIdx.x >> 5;
    if (lane == 0) sbuf[w] = v;
    __syncthreads();
    int nw = blockDim.x >> 5;
    v = (threadIdx.x < nw) ? sbuf[threadIdx.x] : 0;
    if (w == 0) {
        #pragma unroll
        for (int o = 16; o > 0; o >>= 1) v += __shfl_down_sync(0xffffffffu, v, o);
    }
    return v;
}

// ---------------- kernel 0: init accumulators ----------------
__global__ void k_init() {
    int i = blockIdx.x * blockDim.x + threadIdx.x;
    if (i < BB * OO) g_bestprior[i] = 0xFFFFFFFFull;  // ratio=0, idx=0 (stored ~idx)
    if (i < BB) g_numpos[i] = 0;
    if (i < 4) g_accum[i] = 0.f;
}

// ---------------- kernel 1: IOU matching (division-free fast path) ----------------
// Per prior: best truth (max/argmax over 50 truths) stored as (inter, den) pair.
// Per truth: best prior via gated exact division + packed 64-bit atomicMax.
__global__ void k_match(const float* __restrict__ priors, const float* __restrict__ targets) {
    const int b = blockIdx.y;
    __shared__ float4 s_t[OO];
    __shared__ float s_a[OO];
    __shared__ unsigned int s_gate[OO];
    const int tid = threadIdx.x;
    if (tid < OO) {
        const float* tp = targets + ((size_t)b * OO + tid) * 5;
        float4 t;
        t.x = tp[0]; t.y = tp[1]; t.z = tp[2]; t.w = tp[3];
        s_t[tid] = t;
        s_a[tid] = (t.z - t.x) * (t.w - t.y);
        s_gate[tid] = 0u;
    }
    __syncthreads();

    const int p0 = blockIdx.x * (blockDim.x * 2) + tid;
    #pragma unroll
    for (int r = 0; r < 2; r++) {
        const int p = p0 + r * blockDim.x;
        const float4 pr = reinterpret_cast<const float4*>(priors)[p];
        const float px1 = pr.x - pr.z * 0.5f, py1 = pr.y - pr.w * 0.5f;
        const float px2 = pr.x + pr.z * 0.5f, py2 = pr.y + pr.w * 0.5f;
        const float areab = (px2 - px1) * (py2 - py1);

        float bi = -1.0f, bd = 1.0f;  // guarantees update at t=0
        int bt = 0;
        #pragma unroll 5
        for (int t = 0; t < OO; t++) {
            const float4 tb = s_t[t];
            const float ltx = fmaxf(tb.x, px1), lty = fmaxf(tb.y, py1);
            const float rbx = fminf(tb.z, px2), rby = fminf(tb.w, py2);
            const float w = fmaxf(rbx - ltx, 0.f), h = fmaxf(rby - lty, 0.f);
            const float inter = w * h;
            const float den = s_a[t] + areab - inter;
            // argmax over truths, first occurrence kept (strict >)
            if (inter * bd > bi * den) { bi = inter; bd = den; bt = t; }
            // gated best-prior-per-truth (rare path)
            const float rg = __uint_as_float(*(volatile unsigned int*)&s_gate[t]);
            if (inter > rg * den) {
                const float ratio = inter / den;
                const unsigned int rb2 = __float_as_uint(ratio);
                const unsigned int old = atomicMax(&s_gate[t], rb2);
                if (rb2 > old) {
                    unsigned long long pk =
                        ((unsigned long long)rb2 << 32) | (unsigned int)(~p);
                    atomicMax(&g_bestprior[b * OO + t], pk);
                }
            }
        }
        const size_t off = (size_t)b * PP + p;
        g_inter[off] = bi;
        g_den[off] = bd;
        g_tidx[off] = (unsigned char)bt;
    }
}

// ---------------- kernel 2: per-truth best-prior override ----------------
__global__ void k_override() {
    const int b = blockIdx.x * blockDim.x + threadIdx.x;
    if (b >= BB) return;
    for (int t = 0; t < OO; t++) {  // ascending: last-write-wins on dup priors
        const unsigned long long pk = g_bestprior[b * OO + t];
        const unsigned int p = ~(unsigned int)(pk & 0xFFFFFFFFu);
        if (p < PP) {
            const size_t off = (size_t)b * PP + p;
            g_inter[off] = 2.f;   // ovl := 2.0
            g_den[off] = 1.f;
            g_tidx[off] = (unsigned char)t;
        }
    }
}

// ---------------- kernel 3: per-prior loss terms ----------------
__global__ void k_loss(const float* __restrict__ arm_loc, const float* __restrict__ arm_conf,
                       const float* __restrict__ priors, const float* __restrict__ targets) {
    __shared__ float sbufF[32];
    __shared__ int sbufI[32];
    const int b = blockIdx.y;
    const int p = blockIdx.x * blockDim.x + threadIdx.x;
    const size_t off = (size_t)b * PP + p;

    const float inter = g_inter[off];
    const float den = g_den[off];
    const int t = g_tidx[off];

    const float* tb = targets + ((size_t)b * OO + t) * 5;
    const int label = (tb[4] >= 0.f) ? 1 : 0;
    const bool thr = (inter >= 0.5f * den);  // ovl >= THRESH
    const int conf_t = thr ? label : 0;
    const bool pos = conf_t > 0;

    const float2 cc = reinterpret_cast<const float2*>(arm_conf)[off];
    const float c0 = cc.x, c1 = cc.y;
    const float m = fmaxf(c0, c1);
    const float lse = m + logf(expf(c0 - m) + expf(c1 - m));
    const float picked = (conf_t == 0) ? c0 : c1;
    const float lc = lse - picked;
    g_lcmine[off] = pos ? 0.f : lc;

    float ll = 0.f, plc = 0.f;
    if (pos) {
        plc = lc;
        const float x1 = tb[0], y1 = tb[1], x2 = tb[2], y2 = tb[3];
        const float4 pr = reinterpret_cast<const float4*>(priors)[p];
        const float gcx = ((x1 + x2) * 0.5f - pr.x) / (0.1f * pr.z);
        const float gcy = ((y1 + y2) * 0.5f - pr.y) / (0.1f * pr.w);
        const float gw = logf((x2 - x1) / pr.z) / 0.2f;
        const float gh = logf((y2 - y1) / pr.w) / 0.2f;
        const float4 al = reinterpret_cast<const float4*>(arm_loc)[off];
        const float d0 = al.x - gcx, d1 = al.y - gcy, d2 = al.z - gw, d3 = al.w - gh;
        #define SL1(d) (fabsf(d) < 1.f ? 0.5f * (d) * (d) : fabsf(d) - 0.5f)
        ll = SL1(d0) + SL1(d1) + SL1(d2) + SL1(d3);
        #undef SL1
    }

    const float llT = blockReduceSumF(ll, sbufF);
    const float plcT = blockReduceSumF(plc, sbufF);
    const int cntT = blockReduceSumI(pos ? 1 : 0, sbufI);
    if (threadIdx.x == 0) {
        if (llT != 0.f) atomicAdd(&g_accum[0], llT);
        if (plcT != 0.f) atomicAdd(&g_accum[1], plcT);
        if (cntT != 0) atomicAdd(&g_numpos[b], cntT);
    }
}

// ---------------- kernel 4: per-batch top-K sum via radix select ----------------
__global__ void k_select() {
    extern __shared__ unsigned int s_keys[];  // PP uint32 = 128KB
    __shared__ int hist[256];
    __shared__ int s_sel, s_rem;
    __shared__ float sbufF[32];
    __shared__ int sbufI[32];
    const int b = blockIdx.x;
    const int tid = threadIdx.x;

    const int np = g_numpos[b];
    int K = 3 * np;
    if (K > PP - 1) K = PP - 1;
    if (K <= 0) return;  // uniform across block

    for (int i = tid; i < PP; i += blockDim.x)
        s_keys[i] = __float_as_uint(g_lcmine[(size_t)b * PP + i]);  // all >= 0 -> monotone bits
    __syncthreads();

    unsigned int prefix = 0, mask = 0;
    int remaining = K;
    for (int pass = 0; pass < 4; pass++) {
        const int shift = 24 - 8 * pass;
        for (int i = tid; i < 256; i += blockDim.x) hist[i] = 0;
        __syncthreads();
        for (int i = tid; i < PP; i += blockDim.x) {
            const unsigned int k = s_keys[i];
            if ((k & mask) == prefix) atomicAdd(&hist[(k >> shift) & 0xFFu], 1);
        }
        __syncthreads();
        if (tid == 0) {
            int c = 0, sel = 0, rem = remaining;
            for (int d = 255; d >= 0; d--) {
                const int nc = c + hist[d];
                if (nc >= remaining) { sel = d; rem = remaining - c; break; }
                c = nc;
            }
            s_sel = sel; s_rem = rem;
        }
        __syncthreads();
        prefix |= ((unsigned int)s_sel) << shift;
        mask |= 0xFFu << shift;
        remaining = s_rem;
        __syncthreads();
    }

    const float kth = __uint_as_float(prefix);
    float sum = 0.f;
    int cnt = 0;
    for (int i = tid; i < PP; i += blockDim.x) {
        const unsigned int k = s_keys[i];
        if (k > prefix) { sum += __uint_as_float(k); cnt++; }
    }
    const float sumT = blockReduceSumF(sum, sbufF);
    const int cntT = blockReduceSumI(cnt, sbufI);
    if (tid == 0) {
        const float total = sumT + (float)(K - cntT) * kth;
        atomicAdd(&g_accum[2], total);
    }
}

// ---------------- kernel 5: final combine ----------------
__global__ void k_final(float* __restrict__ out) {
    if (threadIdx.x == 0) {
        int N = 0;
        for (int b = 0; b < BB; b++) N += g_numpos[b];
        const float fN = (float)N;
        out[0] = g_accum[0] / fN;
        out[1] = (g_accum[1] + g_accum[2]) / fN;
    }
}

// ---------------- launch ----------------
extern "C" void kernel_launch(void* const* d_in, const int* in_sizes, int n_in,
                              void* d_out, int out_size) {
    const float* arm_loc  = (const float*)d_in[0];
    const float* arm_conf = (const float*)d_in[1];
    // d_in[2], d_in[3]: odm_loc / odm_conf unused by the reference loss
    const float* priors   = (const float*)d_in[4];
    const float* targets  = (const float*)d_in[5];
    float* out = (float*)d_out;

    cudaFuncSetAttribute(k_select, cudaFuncAttributeMaxDynamicSharedMemorySize, PP * 4);

    k_init<<<(BB * OO + 255) / 256, 256>>>();
    dim3 g1(PP / (256 * 2), BB);
    k_match<<<g1, 256>>>(priors, targets);
    k_override<<<1, BB>>>();
    dim3 g3(PP / 256, BB);
    k_loss<<<g3, 256>>>(arm_loc, arm_conf, priors, targets);
    k_select<<<BB, 1024, PP * 4>>>();
    k_final<<<1, 32>>>(out);
}